// round 1
// baseline (speedup 1.0000x reference)
#include <cuda_runtime.h>
#include <cmath>

#define NN 50000
#define EE 800000

// ---------------- global scratch (__device__ arrays: allocation-free) -------------
__device__ __align__(16) float g_etab[5 * 68];          // bond-type table (incl. b1), padded rows
__device__ __align__(16) float g_adst[NN * 64];         // xt @ W1_i  per node
__device__ __align__(16) float g_asrc[NN * 64];         // xt @ W1_j  per node
__device__ int   g_deg[NN];
__device__ int   g_rowoff[NN + 1];
__device__ int   g_cursor[NN];
__device__ int   g_eperm[EE];
__device__ __align__(16) float g_h[51200000];           // EE*64 messages, slot-permuted

// ---------------- K0: bond/e tables ----------------------------------------------
__global__ void k0_tables(const float* __restrict__ bond_emb, const float* __restrict__ edge_w,
                          const float* __restrict__ edge_b, const float* __restrict__ pre_w1,
                          const float* __restrict__ pre_b1) {
    __shared__ float eraw[5 * 16];
    int tid = threadIdx.x;
    if (tid < 80) {
        int b = tid / 16, f = tid % 16;
        float acc = edge_b[f];
        for (int h = 0; h < 64; h++) acc += bond_emb[b * 64 + h] * edge_w[h * 16 + f];
        eraw[b * 16 + f] = acc;
    }
    __syncthreads();
    for (int i = tid; i < 340; i += blockDim.x) g_etab[i] = 0.f;   // init padding
    __syncthreads();
    for (int i = tid; i < 320; i += blockDim.x) {
        int b = i / 64, r = i % 64, t = r / 16, g = r % 16;
        float acc = pre_b1[t * 16 + g];
        for (int f = 0; f < 16; f++) acc += eraw[b * 16 + f] * pre_w1[t * 768 + (32 + f) * 16 + g];
        g_etab[b * 68 + t * 16 + g] = acc;
    }
}

// ---------------- K1: per-node pre-transforms (xt @ W1_i , xt @ W1_j) -------------
__global__ void k1_nodepre(const float* __restrict__ atom_x, const float* __restrict__ pre_w1) {
    __shared__ float w1s[3072];
    for (int i = threadIdx.x; i < 3072; i += blockDim.x) w1s[i] = pre_w1[i];
    __syncthreads();
    int n = blockIdx.x * blockDim.x + threadIdx.x;
    if (n >= NN) return;
    float x[64];
    const float4* xp = (const float4*)(atom_x + (size_t)n * 64);
#pragma unroll
    for (int i = 0; i < 16; i++) {
        float4 v = xp[i];
        x[4 * i] = v.x; x[4 * i + 1] = v.y; x[4 * i + 2] = v.z; x[4 * i + 3] = v.w;
    }
#pragma unroll
    for (int t = 0; t < 4; t++) {
        float ad[16], as[16];
#pragma unroll
        for (int g = 0; g < 16; g++) { ad[g] = 0.f; as[g] = 0.f; }
#pragma unroll
        for (int f = 0; f < 16; f++) {
            float xv = x[t * 16 + f];
#pragma unroll
            for (int g = 0; g < 16; g++) {
                ad[g] += xv * w1s[t * 768 + f * 16 + g];
                as[g] += xv * w1s[t * 768 + (16 + f) * 16 + g];
            }
        }
        float4* dp = (float4*)(g_adst + (size_t)n * 64 + t * 16);
        float4* sp = (float4*)(g_asrc + (size_t)n * 64 + t * 16);
#pragma unroll
        for (int q = 0; q < 4; q++) {
            dp[q] = make_float4(ad[4 * q], ad[4 * q + 1], ad[4 * q + 2], ad[4 * q + 3]);
            sp[q] = make_float4(as[4 * q], as[4 * q + 1], as[4 * q + 2], as[4 * q + 3]);
        }
    }
}

// ---------------- K2: degree histogram --------------------------------------------
__global__ void kz_zero() {
    int i = blockIdx.x * blockDim.x + threadIdx.x;
    if (i < NN) g_deg[i] = 0;
}
__global__ void k2_count(const int* __restrict__ dst) {
    int e = blockIdx.x * blockDim.x + threadIdx.x;
    if (e < EE) atomicAdd(&g_deg[dst[e]], 1);
}

// ---------------- K3: exclusive scan (single block) -------------------------------
__global__ void k3_scan() {
    __shared__ int wsum[32];
    __shared__ int s_tot;
    int tid = threadIdx.x, lane = tid & 31, wid = tid >> 5;
    int running = 0;
    for (int base = 0; base < NN; base += 1024) {
        int i = base + tid;
        int v = (i < NN) ? g_deg[i] : 0;
        int incl = v;
#pragma unroll
        for (int d = 1; d < 32; d <<= 1) {
            int t2 = __shfl_up_sync(0xFFFFFFFFu, incl, d);
            if (lane >= d) incl += t2;
        }
        if (lane == 31) wsum[wid] = incl;
        __syncthreads();
        if (wid == 0) {
            int wv = wsum[lane];
            int wi = wv;
#pragma unroll
            for (int d = 1; d < 32; d <<= 1) {
                int t2 = __shfl_up_sync(0xFFFFFFFFu, wi, d);
                if (lane >= d) wi += t2;
            }
            wsum[lane] = wi - wv;
            if (lane == 31) s_tot = wi;
        }
        __syncthreads();
        int off = running + wsum[wid] + incl - v;
        if (i < NN) { g_rowoff[i] = off; g_cursor[i] = off; }
        running += s_tot;
        __syncthreads();
    }
    if (tid == 0) g_rowoff[NN] = running;
}

// ---------------- K4: bucket permutation ------------------------------------------
__global__ void k4_permute(const int* __restrict__ dst) {
    int e = blockIdx.x * blockDim.x + threadIdx.x;
    if (e >= EE) return;
    int slot = atomicAdd(&g_cursor[dst[e]], 1);
    g_eperm[slot] = e;
}

// ---------------- K5: edge messages (slot order) ----------------------------------
__global__ void k5_edge(const int* __restrict__ src, const int* __restrict__ dst,
                        const int* __restrict__ bond, const float* __restrict__ pre_w2,
                        const float* __restrict__ pre_b2) {
    __shared__ float w2s[1024];
    __shared__ float b2s[64];
    __shared__ __align__(16) float etabs[340];
    for (int i = threadIdx.x; i < 1024; i += blockDim.x) w2s[i] = pre_w2[i];
    for (int i = threadIdx.x; i < 64; i += blockDim.x) b2s[i] = pre_b2[i];
    for (int i = threadIdx.x; i < 340; i += blockDim.x) etabs[i] = g_etab[i];
    __syncthreads();
    int s = blockIdx.x * blockDim.x + threadIdx.x;
    if (s >= EE) return;
    int e = g_eperm[s];
    int ns = src[e], nd = dst[e], b = bond[e];
    const float4* pd = (const float4*)(g_adst + (size_t)nd * 64);
    const float4* ps = (const float4*)(g_asrc + (size_t)ns * 64);
    const float4* pe = (const float4*)(etabs + b * 68);
    float4* outp = (float4*)(g_h + (size_t)s * 64);
#pragma unroll
    for (int t = 0; t < 4; t++) {
        float hid[16];
#pragma unroll
        for (int q = 0; q < 4; q++) {
            float4 a = pd[t * 4 + q], c = ps[t * 4 + q], ev = pe[t * 4 + q];
            hid[4 * q + 0] = fmaxf(a.x + c.x + ev.x, 0.f);
            hid[4 * q + 1] = fmaxf(a.y + c.y + ev.y, 0.f);
            hid[4 * q + 2] = fmaxf(a.z + c.z + ev.z, 0.f);
            hid[4 * q + 3] = fmaxf(a.w + c.w + ev.w, 0.f);
        }
        float acc[16];
#pragma unroll
        for (int g = 0; g < 16; g++) acc[g] = b2s[t * 16 + g];
#pragma unroll
        for (int f = 0; f < 16; f++) {
            float hv = hid[f];
#pragma unroll
            for (int g = 0; g < 16; g++) acc[g] += hv * w2s[t * 256 + f * 16 + g];
        }
#pragma unroll
        for (int q = 0; q < 4; q++)
            outp[t * 4 + q] = make_float4(acc[4 * q], acc[4 * q + 1], acc[4 * q + 2], acc[4 * q + 3]);
    }
}

// ---------------- K6: gather + post-MLP + lin + LN + residual ---------------------
// smem: w1 (4*4112) | w2 (1024) | lin (4096) | bias (320) | per-warp scratch (8*512)
#define K6_SMEM_FLOATS (4 * 4112 + 1024 + 4096 + 320 + 8 * 512)

__global__ void k6_node(const float* __restrict__ atom_x,
                        const float* __restrict__ post_w1, const float* __restrict__ post_b1,
                        const float* __restrict__ post_w2, const float* __restrict__ post_b2,
                        const float* __restrict__ lin_w, const float* __restrict__ lin_b,
                        const float* __restrict__ ln_g, const float* __restrict__ ln_b,
                        float* __restrict__ out, float avg_log) {
    extern __shared__ float sm[];
    float* w1s  = sm;                    // padded tower stride 4112
    float* w2s  = w1s + 4 * 4112;
    float* lws  = w2s + 1024;
    float* bias = lws + 4096;            // [b1(64) b2(64) lb(64) g(64) b(64)]
    float* scratch = bias + 320;

    int tid = threadIdx.x;
    for (int i = tid; i < 16384; i += 256) {
        int t = i >> 12;
        w1s[t * 4112 + (i & 4095)] = post_w1[i];
    }
    for (int i = tid; i < 1024; i += 256) w2s[i] = post_w2[i];
    for (int i = tid; i < 4096; i += 256) lws[i] = lin_w[i];
    if (tid < 64) {
        bias[tid]       = post_b1[tid];
        bias[64 + tid]  = post_b2[tid];
        bias[128 + tid] = lin_b[tid];
        bias[192 + tid] = ln_g[tid];
        bias[256 + tid] = ln_b[tid];
    }
    __syncthreads();

    int wid = tid >> 5, lane = tid & 31;
    int n = blockIdx.x * 8 + wid;
    if (n >= NN) return;

    float* ws    = scratch + wid * 512;
    float* xts   = ws;          // 64
    float* basev = ws + 64;     // 320 : per tower [sum mean mn mx std] * 16
    float* hids  = ws + 384;    // 64
    float* hid2s = ws + 448;    // 64

    float x1 = atom_x[(size_t)n * 64 + lane];
    float x2 = atom_x[(size_t)n * 64 + lane + 32];
    xts[lane] = x1; xts[lane + 32] = x2;

    int r0 = g_rowoff[n], r1 = g_rowoff[n + 1];
    int deg = r1 - r0;
    float sa1 = 0.f, sa2 = 0.f, q1 = 0.f, q2 = 0.f;
    float mn1 = INFINITY, mn2 = INFINITY, mx1 = -INFINITY, mx2 = -INFINITY;
    for (int i = r0; i < r1; i++) {
        float v1 = g_h[(size_t)i * 64 + lane];
        float v2 = g_h[(size_t)i * 64 + lane + 32];
        sa1 += v1; sa2 += v2; q1 += v1 * v1; q2 += v2 * v2;
        mn1 = fminf(mn1, v1); mn2 = fminf(mn2, v2);
        mx1 = fmaxf(mx1, v1); mx2 = fmaxf(mx2, v2);
    }
    float cc = fmaxf((float)deg, 1.f);
    float inv = 1.f / cc;
    float mean1 = sa1 * inv, mean2 = sa2 * inv;
    float std1 = sqrtf(fmaxf(q1 * inv - mean1 * mean1, 0.f) + 1e-5f);
    float std2 = sqrtf(fmaxf(q2 * inv - mean2 * mean2, 0.f) + 1e-5f);
    if (deg == 0) { mn1 = 0.f; mn2 = 0.f; mx1 = 0.f; mx2 = 0.f; }

    int t1 = lane >> 4, f1 = lane & 15;
    int t2 = t1 + 2;
    {
        float* bp = basev + t1 * 80 + f1;
        bp[0] = sa1; bp[16] = mean1; bp[32] = mn1; bp[48] = mx1; bp[64] = std1;
        float* cp = basev + t2 * 80 + f1;
        cp[0] = sa2; cp[16] = mean2; cp[32] = mn2; cp[48] = mx2; cp[64] = std2;
    }
    __syncwarp();

    float ldv = logf(cc + 1.f);
    float sc1 = ldv / avg_log;
    float sc2 = avg_log / ldv;

    // post MLP layer 1: outputs o1=lane (tower t1), o2=lane+32 (tower t2), g=f1
    float acc1 = bias[lane], acc2 = bias[lane + 32];
    const float* w1a = w1s + t1 * 4112;
    const float* w1b = w1s + t2 * 4112;
#pragma unroll
    for (int f = 0; f < 16; f++) {
        acc1 += xts[t1 * 16 + f] * w1a[f * 16 + f1];
        acc2 += xts[t2 * 16 + f] * w1b[f * 16 + f1];
    }
#pragma unroll 4
    for (int k = 0; k < 80; k++) {
        float bv1 = basev[t1 * 80 + k], bv2 = basev[t2 * 80 + k];
        float wc1 = w1a[(16 + k) * 16 + f1] + sc1 * w1a[(96 + k) * 16 + f1] + sc2 * w1a[(176 + k) * 16 + f1];
        float wc2 = w1b[(16 + k) * 16 + f1] + sc1 * w1b[(96 + k) * 16 + f1] + sc2 * w1b[(176 + k) * 16 + f1];
        acc1 += bv1 * wc1;
        acc2 += bv2 * wc2;
    }
    hids[lane] = fmaxf(acc1, 0.f);
    hids[lane + 32] = fmaxf(acc2, 0.f);
    __syncwarp();

    // post MLP layer 2
    float a1 = bias[64 + lane], a2 = bias[64 + lane + 32];
#pragma unroll
    for (int f = 0; f < 16; f++) {
        a1 += hids[t1 * 16 + f] * w2s[t1 * 256 + f * 16 + f1];
        a2 += hids[t2 * 16 + f] * w2s[t2 * 256 + f * 16 + f1];
    }
    hid2s[lane] = a1; hid2s[lane + 32] = a2;
    __syncwarp();

    // final linear (tower mix)
    float l1 = bias[128 + lane], l2 = bias[128 + lane + 32];
#pragma unroll 8
    for (int k = 0; k < 64; k++) {
        float hv = hid2s[k];
        l1 += hv * lws[k * 64 + lane];
        l2 += hv * lws[k * 64 + lane + 32];
    }

    // LayerNorm over 64
    float ssum = l1 + l2;
#pragma unroll
    for (int d = 16; d; d >>= 1) ssum += __shfl_xor_sync(0xFFFFFFFFu, ssum, d);
    float mu = ssum * (1.f / 64.f);
    float d1 = l1 - mu, d2 = l2 - mu;
    float vs = d1 * d1 + d2 * d2;
#pragma unroll
    for (int d = 16; d; d >>= 1) vs += __shfl_xor_sync(0xFFFFFFFFu, vs, d);
    float rstd = rsqrtf(vs * (1.f / 64.f) + 1e-5f);
    float o1 = d1 * rstd * bias[192 + lane] + bias[256 + lane];
    float o2 = d2 * rstd * bias[192 + lane + 32] + bias[256 + lane + 32];

    out[(size_t)n * 64 + lane]      = x1 + fmaxf(o1, 0.f);
    out[(size_t)n * 64 + lane + 32] = x2 + fmaxf(o2, 0.f);
}

// ---------------- launch ----------------------------------------------------------
extern "C" void kernel_launch(void* const* d_in, const int* in_sizes, int n_in,
                              void* d_out, int out_size) {
    const float* atom_x  = (const float*)d_in[0];
    const float* bond_emb= (const float*)d_in[1];
    const float* edge_w  = (const float*)d_in[2];
    const float* edge_b  = (const float*)d_in[3];
    const float* pre_w1  = (const float*)d_in[4];
    const float* pre_b1  = (const float*)d_in[5];
    const float* pre_w2  = (const float*)d_in[6];
    const float* pre_b2  = (const float*)d_in[7];
    const float* post_w1 = (const float*)d_in[8];
    const float* post_b1 = (const float*)d_in[9];
    const float* post_w2 = (const float*)d_in[10];
    const float* post_b2 = (const float*)d_in[11];
    const float* lin_w   = (const float*)d_in[12];
    const float* lin_b   = (const float*)d_in[13];
    const float* ln_g    = (const float*)d_in[14];
    const float* ln_b    = (const float*)d_in[15];
    const int*   bond_x  = (const int*)d_in[16];
    const int*   aei     = (const int*)d_in[17];
    const int*   srcp = aei;
    const int*   dstp = aei + EE;
    float* out = (float*)d_out;

    // AVG_LOG (as in PyG PNAConv degree scaler)
    double md[9] = {0, 5, 15, 30, 25, 15, 7, 2, 1};
    double sacc = 0.0, wacc = 0.0;
    for (int i = 0; i < 9; i++) { sacc += std::log((double)i + 1.0) * md[i]; wacc += md[i]; }
    float avg_log = (float)(sacc / wacc);

    const int k6_smem = K6_SMEM_FLOATS * 4;
    cudaFuncSetAttribute(k6_node, cudaFuncAttributeMaxDynamicSharedMemorySize, k6_smem);

    k0_tables<<<1, 128>>>(bond_emb, edge_w, edge_b, pre_w1, pre_b1);
    k1_nodepre<<<(NN + 127) / 128, 128>>>(atom_x, pre_w1);
    kz_zero<<<(NN + 1023) / 1024, 1024>>>();
    k2_count<<<(EE + 255) / 256, 256>>>(dstp);
    k3_scan<<<1, 1024>>>();
    k4_permute<<<(EE + 255) / 256, 256>>>(dstp);
    k5_edge<<<EE / 128, 128>>>(srcp, dstp, bond_x, pre_w2, pre_b2);
    k6_node<<<NN / 8, 256, k6_smem>>>(atom_x, post_w1, post_b1, post_w2, post_b2,
                                      lin_w, lin_b, ln_g, ln_b, out, avg_log);
}

// round 2
// speedup vs baseline: 1.3252x; 1.3252x over previous
#include <cuda_runtime.h>
#include <cmath>

#define NN 50000
#define EE 800000

// ---------------- global scratch (__device__ arrays: allocation-free) -------------
__device__ __align__(16) float g_etab[5 * 68];          // bond-type table (incl. pre_b1 part), padded rows
__device__ __align__(16) float g_adst[NN * 64];         // xt @ W1_i  per node
__device__ __align__(16) float g_asrc[NN * 64];         // xt @ W1_j  per node
__device__ int   g_deg[NN];
__device__ __align__(16) int g_rowoff[NN + 4];
__device__ __align__(16) int g_cursor[NN + 4];
__device__ int   g_epack[EE];                           // per CSR slot: src | bond<<16
__device__ __align__(16) float g_agg[NN * 320];         // per node: 4 towers x [s mean mn mx std] x 16

// ---------------- K0: bond/e tables ----------------------------------------------
__global__ void k0_tables(const float* __restrict__ bond_emb, const float* __restrict__ edge_w,
                          const float* __restrict__ edge_b, const float* __restrict__ pre_w1,
                          const float* __restrict__ pre_b1) {
    __shared__ float eraw[5 * 16];
    int tid = threadIdx.x;
    if (tid < 80) {
        int b = tid / 16, f = tid % 16;
        float acc = edge_b[f];
        for (int h = 0; h < 64; h++) acc += bond_emb[b * 64 + h] * edge_w[h * 16 + f];
        eraw[b * 16 + f] = acc;
    }
    __syncthreads();
    for (int i = tid; i < 340; i += blockDim.x) g_etab[i] = 0.f;
    __syncthreads();
    for (int i = tid; i < 320; i += blockDim.x) {
        int b = i / 64, r = i % 64, t = r / 16, g = r % 16;
        float acc = pre_b1[t * 16 + g];
        for (int f = 0; f < 16; f++) acc += eraw[b * 16 + f] * pre_w1[t * 768 + (32 + f) * 16 + g];
        g_etab[b * 68 + t * 16 + g] = acc;
    }
}

// ---------------- K1: per-node pre-transforms (xt @ W1_i , xt @ W1_j) -------------
__global__ void k1_nodepre(const float* __restrict__ atom_x, const float* __restrict__ pre_w1) {
    __shared__ float w1s[3072];
    for (int i = threadIdx.x; i < 3072; i += blockDim.x) w1s[i] = pre_w1[i];
    __syncthreads();
    int n = blockIdx.x * blockDim.x + threadIdx.x;
    if (n >= NN) return;
    float x[64];
    const float4* xp = (const float4*)(atom_x + (size_t)n * 64);
#pragma unroll
    for (int i = 0; i < 16; i++) {
        float4 v = xp[i];
        x[4 * i] = v.x; x[4 * i + 1] = v.y; x[4 * i + 2] = v.z; x[4 * i + 3] = v.w;
    }
#pragma unroll
    for (int t = 0; t < 4; t++) {
        float ad[16], as[16];
#pragma unroll
        for (int g = 0; g < 16; g++) { ad[g] = 0.f; as[g] = 0.f; }
#pragma unroll
        for (int f = 0; f < 16; f++) {
            float xv = x[t * 16 + f];
#pragma unroll
            for (int g = 0; g < 16; g++) {
                ad[g] += xv * w1s[t * 768 + f * 16 + g];
                as[g] += xv * w1s[t * 768 + (16 + f) * 16 + g];
            }
        }
        float4* dp = (float4*)(g_adst + (size_t)n * 64 + t * 16);
        float4* sp = (float4*)(g_asrc + (size_t)n * 64 + t * 16);
#pragma unroll
        for (int q = 0; q < 4; q++) {
            dp[q] = make_float4(ad[4 * q], ad[4 * q + 1], ad[4 * q + 2], ad[4 * q + 3]);
            sp[q] = make_float4(as[4 * q], as[4 * q + 1], as[4 * q + 2], as[4 * q + 3]);
        }
    }
}

// ---------------- K2: degree histogram --------------------------------------------
__global__ void kz_zero() {
    int i = blockIdx.x * blockDim.x + threadIdx.x;
    if (i < NN) g_deg[i] = 0;
}
__global__ void k2_count(const int* __restrict__ dst) {
    int e = blockIdx.x * blockDim.x + threadIdx.x;
    if (e < EE) atomicAdd(&g_deg[dst[e]], 1);
}

// ---------------- K3: exclusive scan (single block, int4) -------------------------
__global__ void k3_scan() {
    __shared__ int wsum[32];
    __shared__ int s_tot;
    int tid = threadIdx.x, lane = tid & 31, wid = tid >> 5;
    int running = 0;
    for (int base = 0; base < NN; base += 4096) {
        int i0 = base + tid * 4;
        int4 v = make_int4(0, 0, 0, 0);
        if (i0 < NN) v = *(const int4*)&g_deg[i0];   // NN % 4 == 0 -> all-or-nothing
        int c0 = v.x, c1 = c0 + v.y, c2 = c1 + v.z, c3 = c2 + v.w;
        int tsum = c3;
        int incl = tsum;
#pragma unroll
        for (int d = 1; d < 32; d <<= 1) {
            int t2 = __shfl_up_sync(0xFFFFFFFFu, incl, d);
            if (lane >= d) incl += t2;
        }
        if (lane == 31) wsum[wid] = incl;
        __syncthreads();
        if (wid == 0) {
            int wv = wsum[lane];
            int wi = wv;
#pragma unroll
            for (int d = 1; d < 32; d <<= 1) {
                int t2 = __shfl_up_sync(0xFFFFFFFFu, wi, d);
                if (lane >= d) wi += t2;
            }
            wsum[lane] = wi - wv;
            if (lane == 31) s_tot = wi;
        }
        __syncthreads();
        int off = running + wsum[wid] + incl - tsum;
        if (i0 < NN) {
            int4 o = make_int4(off, off + c0, off + c1, off + c2);
            *(int4*)&g_rowoff[i0] = o;
            *(int4*)&g_cursor[i0] = o;
        }
        running += s_tot;
        __syncthreads();
    }
    if (tid == 0) g_rowoff[NN] = running;
}

// ---------------- K4: bucket permutation + pack -----------------------------------
__global__ void k4_permute(const int* __restrict__ src, const int* __restrict__ dst,
                           const int* __restrict__ bond) {
    int e = blockIdx.x * blockDim.x + threadIdx.x;
    if (e >= EE) return;
    int slot = atomicAdd(&g_cursor[dst[e]], 1);
    g_epack[slot] = src[e] | (bond[e] << 16);
}

// ---------------- K5: fused edge messages + aggregation (warp per node) -----------
__global__ void __launch_bounds__(256) k5_edgeagg(const float* __restrict__ pre_w2,
                                                  const float* __restrict__ pre_b2) {
    __shared__ float w2s[1024];
    __shared__ float b2s[64];
    __shared__ __align__(16) float etabs[340];
    for (int i = threadIdx.x; i < 1024; i += blockDim.x) w2s[i] = pre_w2[i];
    for (int i = threadIdx.x; i < 64; i += blockDim.x) b2s[i] = pre_b2[i];
    for (int i = threadIdx.x; i < 340; i += blockDim.x) etabs[i] = g_etab[i];
    __syncthreads();

    int wid = threadIdx.x >> 5, lane = threadIdx.x & 31;
    int n = blockIdx.x * 8 + wid;
    if (n >= NN) return;

    int t1 = (lane >> 4) & 1, f1 = lane & 15;
    int srcl_base = lane & 16;                 // t1*16

    // per-lane W2 columns: tower t1 -> output f1, tower t1+2 -> output f1
    float w2c1[16], w2c2[16];
#pragma unroll
    for (int f = 0; f < 16; f++) {
        w2c1[f] = w2s[t1 * 256 + f * 16 + f1];
        w2c2[f] = w2s[(t1 + 2) * 256 + f * 16 + f1];
    }
    float b2_1 = b2s[lane], b2_2 = b2s[lane + 32];
    float adst1 = g_adst[(size_t)n * 64 + lane];
    float adst2 = g_adst[(size_t)n * 64 + lane + 32];

    int r0 = g_rowoff[n], r1 = g_rowoff[n + 1];
    float s1 = 0.f, s2 = 0.f, q1 = 0.f, q2 = 0.f;
    float mn1 = INFINITY, mn2 = INFINITY, mx1 = -INFINITY, mx2 = -INFINITY;

    for (int i = r0; i < r1; i += 32) {
        int pk = 0;
        if (i + lane < r1) pk = g_epack[i + lane];
        int cnt = min(32, r1 - i);
        for (int j = 0; j < cnt; j++) {
            int p = __shfl_sync(0xFFFFFFFFu, pk, j);
            int src = p & 0xFFFF;
            int b = p >> 16;
            float as1 = __ldg(&g_asrc[(size_t)src * 64 + lane]);
            float as2 = __ldg(&g_asrc[(size_t)src * 64 + lane + 32]);
            float h1 = fmaxf(adst1 + as1 + etabs[b * 68 + lane], 0.f);
            float h2 = fmaxf(adst2 + as2 + etabs[b * 68 + lane + 32], 0.f);
            float m1 = b2_1, m2 = b2_2;
#pragma unroll
            for (int f = 0; f < 16; f++) {
                float hv1 = __shfl_sync(0xFFFFFFFFu, h1, srcl_base | f);
                float hv2 = __shfl_sync(0xFFFFFFFFu, h2, srcl_base | f);
                m1 += hv1 * w2c1[f];
                m2 += hv2 * w2c2[f];
            }
            s1 += m1; q1 += m1 * m1; mn1 = fminf(mn1, m1); mx1 = fmaxf(mx1, m1);
            s2 += m2; q2 += m2 * m2; mn2 = fminf(mn2, m2); mx2 = fmaxf(mx2, m2);
        }
    }

    int deg = r1 - r0;
    float cc = fmaxf((float)deg, 1.f);
    float inv = 1.f / cc;
    float mean1 = s1 * inv, mean2 = s2 * inv;
    float std1 = sqrtf(fmaxf(q1 * inv - mean1 * mean1, 0.f) + 1e-5f);
    float std2 = sqrtf(fmaxf(q2 * inv - mean2 * mean2, 0.f) + 1e-5f);
    if (deg == 0) { mn1 = 0.f; mn2 = 0.f; mx1 = 0.f; mx2 = 0.f; }

    float* ap = g_agg + (size_t)n * 320 + t1 * 80 + f1;
    ap[0]  = s1;  ap[16] = mean1; ap[32] = mn1; ap[48] = mx1; ap[64] = std1;
    float* cp = g_agg + (size_t)n * 320 + (t1 + 2) * 80 + f1;
    cp[0]  = s2;  cp[16] = mean2; cp[32] = mn2; cp[48] = mx2; cp[64] = std2;
}

// ---------------- K6: post-MLP + lin + LN + residual (warp per node) --------------
// smem: w1 (4*4112) | w2 (1024) | lin (4096) | bias (320) | per-warp scratch (32*512)
#define K6_SMEM_FLOATS (4 * 4112 + 1024 + 4096 + 320 + 32 * 512)

__global__ void __launch_bounds__(1024, 1)
k6_node(const float* __restrict__ atom_x,
        const float* __restrict__ post_w1, const float* __restrict__ post_b1,
        const float* __restrict__ post_w2, const float* __restrict__ post_b2,
        const float* __restrict__ lin_w, const float* __restrict__ lin_b,
        const float* __restrict__ ln_g, const float* __restrict__ ln_b,
        float* __restrict__ out, float avg_log) {
    extern __shared__ float sm[];
    float* w1s  = sm;                    // padded tower stride 4112
    float* w2s  = w1s + 4 * 4112;
    float* lws  = w2s + 1024;
    float* bias = lws + 4096;            // [b1(64) b2(64) lb(64) g(64) b(64)]
    float* scratch = bias + 320;

    int tid = threadIdx.x;
    for (int i = tid; i < 16384; i += 1024) {
        int t = i >> 12;
        w1s[t * 4112 + (i & 4095)] = post_w1[i];
    }
    if (tid < 1024) w2s[tid] = post_w2[tid];
    for (int i = tid; i < 4096; i += 1024) lws[i] = lin_w[i];
    if (tid < 64) {
        bias[tid]       = post_b1[tid];
        bias[64 + tid]  = post_b2[tid];
        bias[128 + tid] = lin_b[tid];
        bias[192 + tid] = ln_g[tid];
        bias[256 + tid] = ln_b[tid];
    }
    __syncthreads();

    int wid = tid >> 5, lane = tid & 31;
    int n = blockIdx.x * 32 + wid;
    if (n >= NN) return;

    float* ws    = scratch + wid * 512;
    float* xts   = ws;          // 64
    float* basev = ws + 64;     // 320
    float* hids  = ws + 384;    // 64
    float* hid2s = ws + 448;    // 64

    float x1 = atom_x[(size_t)n * 64 + lane];
    float x2 = atom_x[(size_t)n * 64 + lane + 32];
    xts[lane] = x1; xts[lane + 32] = x2;

    // stage agg row into smem (coalesced)
    const float* agp = g_agg + (size_t)n * 320;
#pragma unroll
    for (int i = 0; i < 10; i++) basev[lane + 32 * i] = agp[lane + 32 * i];

    int deg = g_deg[n];
    float cc = fmaxf((float)deg, 1.f);
    float ldv = logf(cc + 1.f);
    float sc1 = ldv / avg_log;
    float sc2 = avg_log / ldv;
    __syncwarp();

    int t1 = lane >> 4, f1 = lane & 15;
    int t2 = t1 + 2;

    // post MLP layer 1
    float acc1 = bias[lane], acc2 = bias[lane + 32];
    const float* w1a = w1s + t1 * 4112;
    const float* w1b = w1s + t2 * 4112;
#pragma unroll
    for (int f = 0; f < 16; f++) {
        acc1 += xts[t1 * 16 + f] * w1a[f * 16 + f1];
        acc2 += xts[t2 * 16 + f] * w1b[f * 16 + f1];
    }
#pragma unroll 4
    for (int k = 0; k < 80; k++) {
        float bv1 = basev[t1 * 80 + k], bv2 = basev[t2 * 80 + k];
        float wc1 = w1a[(16 + k) * 16 + f1] + sc1 * w1a[(96 + k) * 16 + f1] + sc2 * w1a[(176 + k) * 16 + f1];
        float wc2 = w1b[(16 + k) * 16 + f1] + sc1 * w1b[(96 + k) * 16 + f1] + sc2 * w1b[(176 + k) * 16 + f1];
        acc1 += bv1 * wc1;
        acc2 += bv2 * wc2;
    }
    hids[lane] = fmaxf(acc1, 0.f);
    hids[lane + 32] = fmaxf(acc2, 0.f);
    __syncwarp();

    // post MLP layer 2
    float a1 = bias[64 + lane], a2 = bias[64 + lane + 32];
#pragma unroll
    for (int f = 0; f < 16; f++) {
        a1 += hids[t1 * 16 + f] * w2s[t1 * 256 + f * 16 + f1];
        a2 += hids[t2 * 16 + f] * w2s[t2 * 256 + f * 16 + f1];
    }
    hid2s[lane] = a1; hid2s[lane + 32] = a2;
    __syncwarp();

    // final linear (tower mix)
    float l1 = bias[128 + lane], l2 = bias[128 + lane + 32];
#pragma unroll 8
    for (int k = 0; k < 64; k++) {
        float hv = hid2s[k];
        l1 += hv * lws[k * 64 + lane];
        l2 += hv * lws[k * 64 + lane + 32];
    }

    // LayerNorm over 64
    float ssum = l1 + l2;
#pragma unroll
    for (int d = 16; d; d >>= 1) ssum += __shfl_xor_sync(0xFFFFFFFFu, ssum, d);
    float mu = ssum * (1.f / 64.f);
    float d1 = l1 - mu, d2 = l2 - mu;
    float vs = d1 * d1 + d2 * d2;
#pragma unroll
    for (int d = 16; d; d >>= 1) vs += __shfl_xor_sync(0xFFFFFFFFu, vs, d);
    float rstd = rsqrtf(vs * (1.f / 64.f) + 1e-5f);
    float o1 = d1 * rstd * bias[192 + lane] + bias[256 + lane];
    float o2 = d2 * rstd * bias[192 + lane + 32] + bias[256 + lane + 32];

    out[(size_t)n * 64 + lane]      = x1 + fmaxf(o1, 0.f);
    out[(size_t)n * 64 + lane + 32] = x2 + fmaxf(o2, 0.f);
}

// ---------------- launch ----------------------------------------------------------
extern "C" void kernel_launch(void* const* d_in, const int* in_sizes, int n_in,
                              void* d_out, int out_size) {
    const float* atom_x  = (const float*)d_in[0];
    const float* bond_emb= (const float*)d_in[1];
    const float* edge_w  = (const float*)d_in[2];
    const float* edge_b  = (const float*)d_in[3];
    const float* pre_w1  = (const float*)d_in[4];
    const float* pre_b1  = (const float*)d_in[5];
    const float* pre_w2  = (const float*)d_in[6];
    const float* pre_b2  = (const float*)d_in[7];
    const float* post_w1 = (const float*)d_in[8];
    const float* post_b1 = (const float*)d_in[9];
    const float* post_w2 = (const float*)d_in[10];
    const float* post_b2 = (const float*)d_in[11];
    const float* lin_w   = (const float*)d_in[12];
    const float* lin_b   = (const float*)d_in[13];
    const float* ln_g    = (const float*)d_in[14];
    const float* ln_b    = (const float*)d_in[15];
    const int*   bond_x  = (const int*)d_in[16];
    const int*   aei     = (const int*)d_in[17];
    const int*   srcp = aei;
    const int*   dstp = aei + EE;
    float* out = (float*)d_out;

    double md[9] = {0, 5, 15, 30, 25, 15, 7, 2, 1};
    double sacc = 0.0, wacc = 0.0;
    for (int i = 0; i < 9; i++) { sacc += std::log((double)i + 1.0) * md[i]; wacc += md[i]; }
    float avg_log = (float)(sacc / wacc);

    const int k6_smem = K6_SMEM_FLOATS * 4;
    cudaFuncSetAttribute(k6_node, cudaFuncAttributeMaxDynamicSharedMemorySize, k6_smem);

    k0_tables<<<1, 128>>>(bond_emb, edge_w, edge_b, pre_w1, pre_b1);
    k1_nodepre<<<(NN + 127) / 128, 128>>>(atom_x, pre_w1);
    kz_zero<<<(NN + 1023) / 1024, 1024>>>();
    k2_count<<<(EE + 255) / 256, 256>>>(dstp);
    k3_scan<<<1, 1024>>>();
    k4_permute<<<(EE + 255) / 256, 256>>>(srcp, dstp, bond_x);
    k5_edgeagg<<<(NN + 7) / 8, 256>>>(pre_w2, pre_b2);
    k6_node<<<(NN + 31) / 32, 1024, k6_smem>>>(atom_x, post_w1, post_b1, post_w2, post_b2,
                                               lin_w, lin_b, ln_g, ln_b, out, avg_log);
}

// round 3
// speedup vs baseline: 1.7163x; 1.2951x over previous
#include <cuda_runtime.h>
#include <cmath>

#define NN 50000
#define EE 800000

// ---------------- global scratch ---------------------------------------------------
__device__ __align__(16) float g_etab[5 * 68];
__device__ __align__(16) float g_adst[NN * 64];
__device__ __align__(16) float g_asrc[NN * 64];
__device__ int   g_deg[NN];
__device__ __align__(16) int g_rowoff[NN + 4];
__device__ __align__(16) int g_cursor[NN + 4];
__device__ int   g_epack[EE];                           // per CSR slot: src | bond<<16
__device__ __align__(16) float g_agg[NN * 320];

// ---------------- K0: bond/e tables ------------------------------------------------
__global__ void k0_tables(const float* __restrict__ bond_emb, const float* __restrict__ edge_w,
                          const float* __restrict__ edge_b, const float* __restrict__ pre_w1,
                          const float* __restrict__ pre_b1) {
    __shared__ float eraw[5 * 16];
    int tid = threadIdx.x;
    if (tid < 80) {
        int b = tid / 16, f = tid % 16;
        float acc = edge_b[f];
        for (int h = 0; h < 64; h++) acc += bond_emb[b * 64 + h] * edge_w[h * 16 + f];
        eraw[b * 16 + f] = acc;
    }
    __syncthreads();
    for (int i = tid; i < 340; i += blockDim.x) g_etab[i] = 0.f;
    __syncthreads();
    for (int i = tid; i < 320; i += blockDim.x) {
        int b = i / 64, r = i % 64, t = r / 16, g = r % 16;
        float acc = pre_b1[t * 16 + g];
        for (int f = 0; f < 16; f++) acc += eraw[b * 16 + f] * pre_w1[t * 768 + (32 + f) * 16 + g];
        g_etab[b * 68 + t * 16 + g] = acc;
    }
}

// ---------------- K1: per-node pre-transforms --------------------------------------
__global__ void k1_nodepre(const float* __restrict__ atom_x, const float* __restrict__ pre_w1) {
    __shared__ float w1s[3072];
    for (int i = threadIdx.x; i < 3072; i += blockDim.x) w1s[i] = pre_w1[i];
    __syncthreads();
    int n = blockIdx.x * blockDim.x + threadIdx.x;
    if (n >= NN) return;
    float x[64];
    const float4* xp = (const float4*)(atom_x + (size_t)n * 64);
#pragma unroll
    for (int i = 0; i < 16; i++) {
        float4 v = xp[i];
        x[4 * i] = v.x; x[4 * i + 1] = v.y; x[4 * i + 2] = v.z; x[4 * i + 3] = v.w;
    }
#pragma unroll
    for (int t = 0; t < 4; t++) {
        float ad[16], as[16];
#pragma unroll
        for (int g = 0; g < 16; g++) { ad[g] = 0.f; as[g] = 0.f; }
#pragma unroll
        for (int f = 0; f < 16; f++) {
            float xv = x[t * 16 + f];
#pragma unroll
            for (int g = 0; g < 16; g++) {
                ad[g] += xv * w1s[t * 768 + f * 16 + g];
                as[g] += xv * w1s[t * 768 + (16 + f) * 16 + g];
            }
        }
        float4* dp = (float4*)(g_adst + (size_t)n * 64 + t * 16);
        float4* sp = (float4*)(g_asrc + (size_t)n * 64 + t * 16);
#pragma unroll
        for (int q = 0; q < 4; q++) {
            dp[q] = make_float4(ad[4 * q], ad[4 * q + 1], ad[4 * q + 2], ad[4 * q + 3]);
            sp[q] = make_float4(as[4 * q], as[4 * q + 1], as[4 * q + 2], as[4 * q + 3]);
        }
    }
}

// ---------------- K2: degree histogram ---------------------------------------------
__global__ void kz_zero() {
    int i = blockIdx.x * blockDim.x + threadIdx.x;
    if (i < NN) g_deg[i] = 0;
}
__global__ void k2_count(const int* __restrict__ dst) {
    int e = blockIdx.x * blockDim.x + threadIdx.x;
    if (e < EE) atomicAdd(&g_deg[dst[e]], 1);
}

// ---------------- K3: exclusive scan (single block, int4) --------------------------
__global__ void k3_scan() {
    __shared__ int wsum[32];
    __shared__ int s_tot;
    int tid = threadIdx.x, lane = tid & 31, wid = tid >> 5;
    int running = 0;
    for (int base = 0; base < NN; base += 4096) {
        int i0 = base + tid * 4;
        int4 v = make_int4(0, 0, 0, 0);
        if (i0 < NN) v = *(const int4*)&g_deg[i0];
        int c0 = v.x, c1 = c0 + v.y, c2 = c1 + v.z, c3 = c2 + v.w;
        int tsum = c3;
        int incl = tsum;
#pragma unroll
        for (int d = 1; d < 32; d <<= 1) {
            int t2 = __shfl_up_sync(0xFFFFFFFFu, incl, d);
            if (lane >= d) incl += t2;
        }
        if (lane == 31) wsum[wid] = incl;
        __syncthreads();
        if (wid == 0) {
            int wv = wsum[lane];
            int wi = wv;
#pragma unroll
            for (int d = 1; d < 32; d <<= 1) {
                int t2 = __shfl_up_sync(0xFFFFFFFFu, wi, d);
                if (lane >= d) wi += t2;
            }
            wsum[lane] = wi - wv;
            if (lane == 31) s_tot = wi;
        }
        __syncthreads();
        int off = running + wsum[wid] + incl - tsum;
        if (i0 < NN) {
            int4 o = make_int4(off, off + c0, off + c1, off + c2);
            *(int4*)&g_rowoff[i0] = o;
            *(int4*)&g_cursor[i0] = o;
        }
        running += s_tot;
        __syncthreads();
    }
    if (tid == 0) g_rowoff[NN] = running;
}

// ---------------- K4: bucket permutation + pack ------------------------------------
__global__ void k4_permute(const int* __restrict__ src, const int* __restrict__ dst,
                           const int* __restrict__ bond) {
    int e = blockIdx.x * blockDim.x + threadIdx.x;
    if (e >= EE) return;
    int slot = atomicAdd(&g_cursor[dst[e]], 1);
    g_epack[slot] = src[e] | (bond[e] << 16);
}

// ---------------- K5: fused edge messages + aggregation (warp per node, pipelined) -
__global__ void __launch_bounds__(256) k5_edgeagg(const float* __restrict__ pre_w2,
                                                  const float* __restrict__ pre_b2) {
    __shared__ float w2s[1024];
    __shared__ float b2s[64];
    __shared__ __align__(16) float etabs[340];
    for (int i = threadIdx.x; i < 1024; i += blockDim.x) w2s[i] = pre_w2[i];
    for (int i = threadIdx.x; i < 64; i += blockDim.x) b2s[i] = pre_b2[i];
    for (int i = threadIdx.x; i < 340; i += blockDim.x) etabs[i] = g_etab[i];
    __syncthreads();

    int wid = threadIdx.x >> 5, lane = threadIdx.x & 31;
    int n = blockIdx.x * 8 + wid;
    if (n >= NN) return;

    int t1 = (lane >> 4) & 1, f1 = lane & 15;
    int srcl_base = lane & 16;

    float w2c1[16], w2c2[16];
#pragma unroll
    for (int f = 0; f < 16; f++) {
        w2c1[f] = w2s[t1 * 256 + f * 16 + f1];
        w2c2[f] = w2s[(t1 + 2) * 256 + f * 16 + f1];
    }
    float b2_1 = b2s[lane], b2_2 = b2s[lane + 32];
    float adst1 = g_adst[(size_t)n * 64 + lane];
    float adst2 = g_adst[(size_t)n * 64 + lane + 32];

    int r0 = g_rowoff[n], r1 = g_rowoff[n + 1];
    float s1 = 0.f, s2 = 0.f, q1 = 0.f, q2 = 0.f;
    float mn1 = INFINITY, mn2 = INFINITY, mx1 = -INFINITY, mx2 = -INFINITY;

    for (int i = r0; i < r1; i += 32) {
        int pk = 0;
        if (i + lane < r1) pk = g_epack[i + lane];
        int cnt = min(32, r1 - i);
        // prime pipeline for edge 0
        int p = __shfl_sync(0xFFFFFFFFu, pk, 0);
        float nas1 = __ldg(&g_asrc[(size_t)(p & 0xFFFF) * 64 + lane]);
        float nas2 = __ldg(&g_asrc[(size_t)(p & 0xFFFF) * 64 + lane + 32]);
        float ne1  = etabs[(p >> 16) * 68 + lane];
        float ne2  = etabs[(p >> 16) * 68 + lane + 32];
        for (int j = 0; j < cnt; j++) {
            float as1 = nas1, as2 = nas2, e1 = ne1, e2 = ne2;
            if (j + 1 < cnt) {
                int pn = __shfl_sync(0xFFFFFFFFu, pk, j + 1);
                nas1 = __ldg(&g_asrc[(size_t)(pn & 0xFFFF) * 64 + lane]);
                nas2 = __ldg(&g_asrc[(size_t)(pn & 0xFFFF) * 64 + lane + 32]);
                ne1  = etabs[(pn >> 16) * 68 + lane];
                ne2  = etabs[(pn >> 16) * 68 + lane + 32];
            }
            float h1 = fmaxf(adst1 + as1 + e1, 0.f);
            float h2 = fmaxf(adst2 + as2 + e2, 0.f);
            float m1 = b2_1, m2 = b2_2;
#pragma unroll
            for (int f = 0; f < 16; f++) {
                float hv1 = __shfl_sync(0xFFFFFFFFu, h1, srcl_base | f);
                float hv2 = __shfl_sync(0xFFFFFFFFu, h2, srcl_base | f);
                m1 += hv1 * w2c1[f];
                m2 += hv2 * w2c2[f];
            }
            s1 += m1; q1 += m1 * m1; mn1 = fminf(mn1, m1); mx1 = fmaxf(mx1, m1);
            s2 += m2; q2 += m2 * m2; mn2 = fminf(mn2, m2); mx2 = fmaxf(mx2, m2);
        }
    }

    int deg = r1 - r0;
    float cc = fmaxf((float)deg, 1.f);
    float inv = 1.f / cc;
    float mean1 = s1 * inv, mean2 = s2 * inv;
    float std1 = sqrtf(fmaxf(q1 * inv - mean1 * mean1, 0.f) + 1e-5f);
    float std2 = sqrtf(fmaxf(q2 * inv - mean2 * mean2, 0.f) + 1e-5f);
    if (deg == 0) { mn1 = 0.f; mn2 = 0.f; mx1 = 0.f; mx2 = 0.f; }

    float* ap = g_agg + (size_t)n * 320 + t1 * 80 + f1;
    ap[0]  = s1;  ap[16] = mean1; ap[32] = mn1; ap[48] = mx1; ap[64] = std1;
    float* cp = g_agg + (size_t)n * 320 + (t1 + 2) * 80 + f1;
    cp[0]  = s2;  cp[16] = mean2; cp[32] = mn2; cp[48] = mx2; cp[64] = std2;
}

// ---------------- K6: post-MLP + lin + LN + residual (4 nodes per warp) ------------
// smem: w1 (4*4112) | w2 (1024) | lin (4096) | bias (320) | 16 warps * 2056 scratch
#define K6_WARPS 16
#define K6_WSCR 2056
#define K6_SMEM_FLOATS (4 * 4112 + 1024 + 4096 + 320 + K6_WARPS * K6_WSCR)

__global__ void __launch_bounds__(512, 1)
k6_node(const float* __restrict__ atom_x,
        const float* __restrict__ post_w1, const float* __restrict__ post_b1,
        const float* __restrict__ post_w2, const float* __restrict__ post_b2,
        const float* __restrict__ lin_w, const float* __restrict__ lin_b,
        const float* __restrict__ ln_g, const float* __restrict__ ln_b,
        float* __restrict__ out, float avg_log) {
    extern __shared__ float sm[];
    float* w1s  = sm;                    // padded tower stride 4112
    float* w2s  = w1s + 4 * 4112;
    float* lws  = w2s + 1024;
    float* bias = lws + 4096;            // [b1(64) b2(64) lb(64) g(64) b(64)]
    float* scratch = bias + 320;

    int tid = threadIdx.x;
    for (int i = tid; i < 16384; i += 512) {
        int t = i >> 12;
        w1s[t * 4112 + (i & 4095)] = post_w1[i];
    }
    for (int i = tid; i < 1024; i += 512) w2s[i] = post_w2[i];
    for (int i = tid; i < 4096; i += 512) lws[i] = lin_w[i];
    if (tid < 64) {
        bias[tid]       = post_b1[tid];
        bias[64 + tid]  = post_b2[tid];
        bias[128 + tid] = lin_b[tid];
        bias[192 + tid] = ln_g[tid];
        bias[256 + tid] = ln_b[tid];
    }
    __syncthreads();

    int wid = tid >> 5, lane = tid & 31;
    int nb = blockIdx.x * (K6_WARPS * 4) + wid * 4;     // first node of this warp

    float* ws = scratch + wid * K6_WSCR;
    // layout: xts [4*64] | basev [4*320] @256 | hids [4*64] @1536 | hid2 [4*64] @1792 | sc [8] @2048

    // ---- stage 4 nodes ----
#pragma unroll
    for (int m = 0; m < 4; m++) {
        int n = nb + m;
        if (n < NN) {
            ws[m * 64 + lane]      = atom_x[(size_t)n * 64 + lane];
            ws[m * 64 + lane + 32] = atom_x[(size_t)n * 64 + lane + 32];
            const float* agp = g_agg + (size_t)n * 320;
#pragma unroll
            for (int i = 0; i < 10; i++) ws[256 + m * 320 + lane + 32 * i] = agp[lane + 32 * i];
            if (lane == 0) {
                float cc = fmaxf((float)g_deg[n], 1.f);
                float ldv = logf(cc + 1.f);
                ws[2048 + m * 2]     = ldv / avg_log;
                ws[2048 + m * 2 + 1] = avg_log / ldv;
            }
        }
    }
    __syncwarp();

    int t1 = lane >> 4, f1 = lane & 15;
    int t2 = t1 + 2;
    const float* w1a = w1s + t1 * 4112;
    const float* w1b = w1s + t2 * 4112;

    // ---- layer 1: 3-dot regrouping, 4 nodes batched ----
    float aA[4], aB[4], aC[4], bA[4], bB[4], bC[4];
#pragma unroll
    for (int m = 0; m < 4; m++) { aA[m]=0.f; aB[m]=0.f; aC[m]=0.f; bA[m]=0.f; bB[m]=0.f; bC[m]=0.f; }

#pragma unroll 4
    for (int f = 0; f < 16; f++) {
        float wa = w1a[f * 16 + f1];
        float wb = w1b[f * 16 + f1];
#pragma unroll
        for (int m = 0; m < 4; m++) {
            aA[m] += ws[m * 64 + t1 * 16 + f] * wa;
            bA[m] += ws[m * 64 + t2 * 16 + f] * wb;
        }
    }
#pragma unroll 2
    for (int k = 0; k < 80; k++) {
        float wa1 = w1a[(16 + k) * 16 + f1];
        float wb1 = w1a[(96 + k) * 16 + f1];
        float wc1 = w1a[(176 + k) * 16 + f1];
        float wa2 = w1b[(16 + k) * 16 + f1];
        float wb2 = w1b[(96 + k) * 16 + f1];
        float wc2 = w1b[(176 + k) * 16 + f1];
#pragma unroll
        for (int m = 0; m < 4; m++) {
            float v1 = ws[256 + m * 320 + t1 * 80 + k];
            float v2 = ws[256 + m * 320 + t2 * 80 + k];
            aA[m] += v1 * wa1; aB[m] += v1 * wb1; aC[m] += v1 * wc1;
            bA[m] += v2 * wa2; bB[m] += v2 * wb2; bC[m] += v2 * wc2;
        }
    }
#pragma unroll
    for (int m = 0; m < 4; m++) {
        float sc1 = ws[2048 + m * 2], sc2 = ws[2048 + m * 2 + 1];
        float acc1 = bias[lane]      + aA[m] + sc1 * aB[m] + sc2 * aC[m];
        float acc2 = bias[lane + 32] + bA[m] + sc1 * bB[m] + sc2 * bC[m];
        ws[1536 + m * 64 + lane]      = fmaxf(acc1, 0.f);
        ws[1536 + m * 64 + lane + 32] = fmaxf(acc2, 0.f);
    }
    __syncwarp();

    // ---- layer 2 (batched) ----
    {
        float a1[4], a2[4];
#pragma unroll
        for (int m = 0; m < 4; m++) { a1[m] = bias[64 + lane]; a2[m] = bias[64 + lane + 32]; }
#pragma unroll 4
        for (int f = 0; f < 16; f++) {
            float w_1 = w2s[t1 * 256 + f * 16 + f1];
            float w_2 = w2s[t2 * 256 + f * 16 + f1];
#pragma unroll
            for (int m = 0; m < 4; m++) {
                a1[m] += ws[1536 + m * 64 + t1 * 16 + f] * w_1;
                a2[m] += ws[1536 + m * 64 + t2 * 16 + f] * w_2;
            }
        }
        __syncwarp();
#pragma unroll
        for (int m = 0; m < 4; m++) {
            ws[1792 + m * 64 + lane]      = a1[m];
            ws[1792 + m * 64 + lane + 32] = a2[m];
        }
        __syncwarp();
    }

    // ---- final linear (batched) ----
    float l1[4], l2[4];
#pragma unroll
    for (int m = 0; m < 4; m++) { l1[m] = bias[128 + lane]; l2[m] = bias[128 + lane + 32]; }
#pragma unroll 4
    for (int k = 0; k < 64; k++) {
        float w_1 = lws[k * 64 + lane];
        float w_2 = lws[k * 64 + lane + 32];
#pragma unroll
        for (int m = 0; m < 4; m++) {
            float hv = ws[1792 + m * 64 + k];
            l1[m] += hv * w_1;
            l2[m] += hv * w_2;
        }
    }

    // ---- LayerNorm + ReLU + residual per node ----
#pragma unroll
    for (int m = 0; m < 4; m++) {
        int n = nb + m;
        float v1 = l1[m], v2 = l2[m];
        float ssum = v1 + v2;
#pragma unroll
        for (int d = 16; d; d >>= 1) ssum += __shfl_xor_sync(0xFFFFFFFFu, ssum, d);
        float mu = ssum * (1.f / 64.f);
        float d1 = v1 - mu, d2 = v2 - mu;
        float vs = d1 * d1 + d2 * d2;
#pragma unroll
        for (int d = 16; d; d >>= 1) vs += __shfl_xor_sync(0xFFFFFFFFu, vs, d);
        float rstd = rsqrtf(vs * (1.f / 64.f) + 1e-5f);
        float o1 = d1 * rstd * bias[192 + lane] + bias[256 + lane];
        float o2 = d2 * rstd * bias[192 + lane + 32] + bias[256 + lane + 32];
        if (n < NN) {
            out[(size_t)n * 64 + lane]      = ws[m * 64 + lane]      + fmaxf(o1, 0.f);
            out[(size_t)n * 64 + lane + 32] = ws[m * 64 + lane + 32] + fmaxf(o2, 0.f);
        }
    }
}

// ---------------- launch -----------------------------------------------------------
extern "C" void kernel_launch(void* const* d_in, const int* in_sizes, int n_in,
                              void* d_out, int out_size) {
    const float* atom_x  = (const float*)d_in[0];
    const float* bond_emb= (const float*)d_in[1];
    const float* edge_w  = (const float*)d_in[2];
    const float* edge_b  = (const float*)d_in[3];
    const float* pre_w1  = (const float*)d_in[4];
    const float* pre_b1  = (const float*)d_in[5];
    const float* pre_w2  = (const float*)d_in[6];
    const float* pre_b2  = (const float*)d_in[7];
    const float* post_w1 = (const float*)d_in[8];
    const float* post_b1 = (const float*)d_in[9];
    const float* post_w2 = (const float*)d_in[10];
    const float* post_b2 = (const float*)d_in[11];
    const float* lin_w   = (const float*)d_in[12];
    const float* lin_b   = (const float*)d_in[13];
    const float* ln_g    = (const float*)d_in[14];
    const float* ln_b    = (const float*)d_in[15];
    const int*   bond_x  = (const int*)d_in[16];
    const int*   aei     = (const int*)d_in[17];
    const int*   srcp = aei;
    const int*   dstp = aei + EE;
    float* out = (float*)d_out;

    double md[9] = {0, 5, 15, 30, 25, 15, 7, 2, 1};
    double sacc = 0.0, wacc = 0.0;
    for (int i = 0; i < 9; i++) { sacc += std::log((double)i + 1.0) * md[i]; wacc += md[i]; }
    float avg_log = (float)(sacc / wacc);

    const int k6_smem = K6_SMEM_FLOATS * 4;
    cudaFuncSetAttribute(k6_node, cudaFuncAttributeMaxDynamicSharedMemorySize, k6_smem);

    k0_tables<<<1, 128>>>(bond_emb, edge_w, edge_b, pre_w1, pre_b1);
    k1_nodepre<<<(NN + 127) / 128, 128>>>(atom_x, pre_w1);
    kz_zero<<<(NN + 1023) / 1024, 1024>>>();
    k2_count<<<(EE + 255) / 256, 256>>>(dstp);
    k3_scan<<<1, 1024>>>();
    k4_permute<<<(EE + 255) / 256, 256>>>(srcp, dstp, bond_x);
    k5_edgeagg<<<(NN + 7) / 8, 256>>>(pre_w2, pre_b2);
    k6_node<<<(NN + K6_WARPS * 4 - 1) / (K6_WARPS * 4), 512, k6_smem>>>(
        atom_x, post_w1, post_b1, post_w2, post_b2,
        lin_w, lin_b, ln_g, ln_b, out, avg_log);
}